// round 5
// baseline (speedup 1.0000x reference)
#include <cuda_runtime.h>
#include <cstdint>

// NodeDropout: out[e] = values[e] if neither endpoint is dropped, else 0.
// edge_index: int32 [2, E], values: f32 [E],
// nodes_flag: bool marshaled as int32 [N] (nonzero = dropped). Output: f32 [E].
//
// R4 -> R5: smem bitmask kept (L1tex gather fix); added 2x ILP unroll with
// front-batched 128-bit loads to double in-flight MLP (occ is capped at 50%
// by the 125 KB smem staging, so latency hiding must come from ILP).

static constexpr int MAX_WORDS = 32768;  // supports up to 1,048,576 nodes
__device__ unsigned int g_bits[MAX_WORDS];

// ---- Kernel 1: pack int32 flags -> bitmask ----
__global__ __launch_bounds__(256)
void pack_flags_kernel(const int* __restrict__ flag, int nflags, int nwords) {
    int warp = (blockIdx.x * blockDim.x + threadIdx.x) >> 5;
    int lane = threadIdx.x & 31;
    int nwarps = (gridDim.x * blockDim.x) >> 5;
    for (int w = warp; w < nwords; w += nwarps) {
        int idx = (w << 5) + lane;
        int f = (idx < nflags) ? flag[idx] : 0;
        unsigned int bits = __ballot_sync(0xFFFFFFFFu, f != 0);
        if (lane == 0) g_bits[w] = bits;
    }
}

__device__ __forceinline__ float4 mask4(const unsigned int* s_bits,
                                        int4 s, int4 d, float4 v) {
    unsigned int b0 = (s_bits[((unsigned)s.x) >> 5] >> (s.x & 31)) |
                      (s_bits[((unsigned)d.x) >> 5] >> (d.x & 31));
    unsigned int b1 = (s_bits[((unsigned)s.y) >> 5] >> (s.y & 31)) |
                      (s_bits[((unsigned)d.y) >> 5] >> (d.y & 31));
    unsigned int b2 = (s_bits[((unsigned)s.z) >> 5] >> (s.z & 31)) |
                      (s_bits[((unsigned)d.z) >> 5] >> (d.z & 31));
    unsigned int b3 = (s_bits[((unsigned)s.w) >> 5] >> (s.w & 31)) |
                      (s_bits[((unsigned)d.w) >> 5] >> (d.w & 31));
    float4 o;
    o.x = (b0 & 1u) ? 0.0f : v.x;
    o.y = (b1 & 1u) ? 0.0f : v.y;
    o.z = (b2 & 1u) ? 0.0f : v.z;
    o.w = (b3 & 1u) ? 0.0f : v.w;
    return o;
}

// ---- Kernel 2: persistent, bitmask staged in smem, 2x ILP unroll ----
__global__ __launch_bounds__(1024, 1)
void node_dropout_kernel(const int4* __restrict__ src4,
                         const int4* __restrict__ dst4,
                         const float4* __restrict__ vals,
                         float4* __restrict__ out,
                         int n4, int nwords) {
    extern __shared__ unsigned int s_bits[];

    // Cooperative coalesced load of the bitmask into shared memory.
    for (int w = threadIdx.x; w < nwords; w += blockDim.x)
        s_bits[w] = g_bits[w];
    __syncthreads();

    int stride = gridDim.x * blockDim.x;
    int i = blockIdx.x * blockDim.x + threadIdx.x;

    // Main unrolled loop: both iterations' LDGs issued before any consumer.
    for (; i + stride < n4; i += 2 * stride) {
        int j = i + stride;
        int4   s_a = __ldg(&src4[i]);
        int4   d_a = __ldg(&dst4[i]);
        float4 v_a = __ldg(&vals[i]);
        int4   s_b = __ldg(&src4[j]);
        int4   d_b = __ldg(&dst4[j]);
        float4 v_b = __ldg(&vals[j]);

        out[i] = mask4(s_bits, s_a, d_a, v_a);
        out[j] = mask4(s_bits, s_b, d_b, v_b);
    }
    // Tail
    if (i < n4) {
        int4   s = __ldg(&src4[i]);
        int4   d = __ldg(&dst4[i]);
        float4 v = __ldg(&vals[i]);
        out[i] = mask4(s_bits, s, d, v);
    }
}

extern "C" void kernel_launch(void* const* d_in, const int* in_sizes, int n_in,
                              void* d_out, int out_size) {
    // metadata order: edge_index [2, E] int32, values [E] f32, nodes_flag [N] int32
    const int* edge_index = (const int*)d_in[0];
    const float* values = (const float*)d_in[1];
    const int* nodes_flag = (const int*)d_in[2];
    float* out = (float*)d_out;

    int e = in_sizes[1];            // number of edges (= out_size)
    int nflags = in_sizes[2];       // number of nodes (1,000,000)
    int n4 = e / 4;                 // E divisible by 4
    int nwords = (nflags + 31) / 32;
    size_t smem_bytes = (size_t)nwords * sizeof(unsigned int);

    const int* src = edge_index;        // row 0
    const int* dst = edge_index + e;    // row 1

    pack_flags_kernel<<<256, 256>>>(nodes_flag, nflags, nwords);

    int num_sms = 148;
    cudaDeviceGetAttribute(&num_sms, cudaDevAttrMultiProcessorCount, 0);
    cudaFuncSetAttribute(node_dropout_kernel,
                         cudaFuncAttributeMaxDynamicSharedMemorySize,
                         (int)smem_bytes);

    node_dropout_kernel<<<num_sms, 1024, smem_bytes>>>(
        (const int4*)src, (const int4*)dst, (const float4*)values,
        (float4*)out, n4, nwords);
}

// round 6
// speedup vs baseline: 1.1839x; 1.1839x over previous
#include <cuda_runtime.h>
#include <cstdint>

// NodeDropout: out[e] = values[e] if neither endpoint is dropped, else 0.
// edge_index: int32 [2, E], values: f32 [E], nodes_flag: int32 [N]. Output: f32 [E].
//
// R6: warp-specialized cp.async.bulk pipeline. R5 showed the L1tex wavefront
// queue (nw*n_LDG*nL >> 248) binds when 32 warps front-batch LDG.128s. Streams
// now arrive via the TMA/bulk path into smem (2-stage mbarrier pipeline, 1
// producer warp + 31 consumer warps); consumers only do LDS + bitmask gather
// + STG. Bitmask (125 KB) stays smem-resident as in R4.

static constexpr int MAX_WORDS = 32768;
__device__ unsigned int g_bits[MAX_WORDS];

static constexpr int THREADS      = 1024;
static constexpr int NCONS        = 31;            // consumer warps 0..30
static constexpr int GPT          = NCONS * 32;    // 992 float4-groups per tile
static constexpr int BUF_BYTES    = GPT * 16;      // 15872 B per array per stage
static constexpr int STAGE_BYTES  = 3 * BUF_BYTES; // 47616
static constexpr int NSTAGES      = 2;
static constexpr int MBAR_OFF     = 0;             // full[0],empty[0],full[1],empty[1]
static constexpr int BUF_OFF      = 64;
static constexpr int BITS_OFF     = BUF_OFF + NSTAGES * STAGE_BYTES; // 95296

// ---- PTX helpers ----
__device__ __forceinline__ uint32_t smem_u32(const void* p) {
    return (uint32_t)__cvta_generic_to_shared(p);
}
__device__ __forceinline__ void mbar_init(uint32_t a, uint32_t cnt) {
    asm volatile("mbarrier.init.shared.b64 [%0], %1;" :: "r"(a), "r"(cnt) : "memory");
}
__device__ __forceinline__ void mbar_expect_tx(uint32_t a, uint32_t bytes) {
    asm volatile("mbarrier.arrive.expect_tx.shared.b64 _, [%0], %1;" :: "r"(a), "r"(bytes) : "memory");
}
__device__ __forceinline__ void mbar_arrive(uint32_t a) {
    asm volatile("mbarrier.arrive.shared.b64 _, [%0];" :: "r"(a) : "memory");
}
__device__ __forceinline__ void mbar_wait(uint32_t a, uint32_t parity) {
    uint32_t done = 0;
    while (!done) {
        asm volatile(
            "{\n\t.reg .pred p;\n\t"
            "mbarrier.try_wait.parity.shared.b64 p, [%1], %2;\n\t"
            "selp.b32 %0, 1, 0, p;\n\t}"
            : "=r"(done) : "r"(a), "r"(parity) : "memory");
    }
}
__device__ __forceinline__ void bulk_g2s(uint32_t dst, const void* src,
                                         uint32_t bytes, uint32_t mbar) {
    asm volatile(
        "cp.async.bulk.shared::cluster.global.mbarrier::complete_tx::bytes "
        "[%0], [%1], %2, [%3];"
        :: "r"(dst), "l"(src), "r"(bytes), "r"(mbar) : "memory");
}

// ---- Kernel 1: pack int32 flags -> bitmask ----
__global__ __launch_bounds__(256)
void pack_flags_kernel(const int* __restrict__ flag, int nflags, int nwords) {
    int warp = (blockIdx.x * blockDim.x + threadIdx.x) >> 5;
    int lane = threadIdx.x & 31;
    int nwarps = (gridDim.x * blockDim.x) >> 5;
    for (int w = warp; w < nwords; w += nwarps) {
        int idx = (w << 5) + lane;
        int f = (idx < nflags) ? flag[idx] : 0;
        unsigned int bits = __ballot_sync(0xFFFFFFFFu, f != 0);
        if (lane == 0) g_bits[w] = bits;
    }
}

// ---- Kernel 2: persistent pipelined main kernel ----
__global__ __launch_bounds__(THREADS, 1)
void node_dropout_kernel(const int4* __restrict__ src4,
                         const int4* __restrict__ dst4,
                         const float4* __restrict__ vals,
                         float4* __restrict__ out,
                         int n4, int ntiles, int nwords) {
    extern __shared__ __align__(16) unsigned char smem_raw[];
    unsigned int* s_bits = (unsigned int*)(smem_raw + BITS_OFF);
    uint32_t mbar_base = smem_u32(smem_raw + MBAR_OFF);
    // layout: full[s] at +16*s, empty[s] at +16*s+8
    int tid  = threadIdx.x;
    int warp = tid >> 5;
    int lane = tid & 31;

    // Stage bitmask into smem (coalesced).
    for (int w = tid; w < nwords; w += THREADS)
        s_bits[w] = g_bits[w];

    if (tid == 0) {
        for (int s = 0; s < NSTAGES; s++) {
            mbar_init(mbar_base + 16 * s, 1);         // full: producer expect_tx arrive
            mbar_init(mbar_base + 16 * s + 8, NCONS); // empty: one arrive per consumer warp
        }
    }
    __syncthreads();

    if (warp == NCONS) {
        // ---- Producer warp ----
        int stage = 0, phase = 1;   // fresh barriers pass parity-1 waits
        for (int t = blockIdx.x; t < ntiles; t += gridDim.x) {
            int g0 = t * GPT;
            int cnt = min(GPT, n4 - g0);
            uint32_t bytes = (uint32_t)cnt * 16u;
            if (lane == 0) {
                uint32_t full  = mbar_base + 16 * stage;
                uint32_t empty = full + 8;
                mbar_wait(empty, phase);
                mbar_expect_tx(full, bytes * 3u);
                uint32_t base = smem_u32(smem_raw + BUF_OFF + stage * STAGE_BYTES);
                bulk_g2s(base,                 src4 + g0, bytes, full);
                bulk_g2s(base + BUF_BYTES,     dst4 + g0, bytes, full);
                bulk_g2s(base + 2 * BUF_BYTES, vals + g0, bytes, full);
            }
            if (++stage == NSTAGES) { stage = 0; phase ^= 1; }
        }
    } else {
        // ---- Consumer warps 0..30 ----
        int stage = 0, phase = 0;
        int g = warp * 32 + lane;   // 0..991 within tile
        for (int t = blockIdx.x; t < ntiles; t += gridDim.x) {
            int g0 = t * GPT;
            int cnt = min(GPT, n4 - g0);
            uint32_t full = mbar_base + 16 * stage;
            mbar_wait(full, phase);   // acquire: orders bulk data before LDS

            if (g < cnt) {
                const unsigned char* sb = smem_raw + BUF_OFF + stage * STAGE_BYTES;
                int4   s = ((const int4*)  (sb))[g];
                int4   d = ((const int4*)  (sb + BUF_BYTES))[g];
                float4 v = ((const float4*)(sb + 2 * BUF_BYTES))[g];

                unsigned int b0 = (s_bits[((unsigned)s.x) >> 5] >> (s.x & 31)) |
                                  (s_bits[((unsigned)d.x) >> 5] >> (d.x & 31));
                unsigned int b1 = (s_bits[((unsigned)s.y) >> 5] >> (s.y & 31)) |
                                  (s_bits[((unsigned)d.y) >> 5] >> (d.y & 31));
                unsigned int b2 = (s_bits[((unsigned)s.z) >> 5] >> (s.z & 31)) |
                                  (s_bits[((unsigned)d.z) >> 5] >> (d.z & 31));
                unsigned int b3 = (s_bits[((unsigned)s.w) >> 5] >> (s.w & 31)) |
                                  (s_bits[((unsigned)d.w) >> 5] >> (d.w & 31));

                float4 o;
                o.x = (b0 & 1u) ? 0.0f : v.x;
                o.y = (b1 & 1u) ? 0.0f : v.y;
                o.z = (b2 & 1u) ? 0.0f : v.z;
                o.w = (b3 & 1u) ? 0.0f : v.w;
                out[g0 + g] = o;
            }
            __syncwarp();
            if (lane == 0) mbar_arrive(mbar_base + 16 * stage + 8);  // empty
            if (++stage == NSTAGES) { stage = 0; phase ^= 1; }
        }
    }
}

extern "C" void kernel_launch(void* const* d_in, const int* in_sizes, int n_in,
                              void* d_out, int out_size) {
    // metadata order: edge_index [2, E] int32, values [E] f32, nodes_flag [N] int32
    const int* edge_index = (const int*)d_in[0];
    const float* values = (const float*)d_in[1];
    const int* nodes_flag = (const int*)d_in[2];
    float* out = (float*)d_out;

    int e = in_sizes[1];
    int nflags = in_sizes[2];
    int n4 = e / 4;
    int nwords = (nflags + 31) / 32;
    int ntiles = (n4 + GPT - 1) / GPT;
    size_t smem_bytes = (size_t)BITS_OFF + (size_t)nwords * 4;

    const int* src = edge_index;
    const int* dst = edge_index + e;

    pack_flags_kernel<<<256, 256>>>(nodes_flag, nflags, nwords);

    int num_sms = 148;
    cudaDeviceGetAttribute(&num_sms, cudaDevAttrMultiProcessorCount, 0);
    cudaFuncSetAttribute(node_dropout_kernel,
                         cudaFuncAttributeMaxDynamicSharedMemorySize,
                         (int)smem_bytes);

    node_dropout_kernel<<<num_sms, THREADS, smem_bytes>>>(
        (const int4*)src, (const int4*)dst, (const float4*)values,
        (float4*)out, n4, ntiles, nwords);
}

// round 7
// speedup vs baseline: 1.2198x; 1.0303x over previous
#include <cuda_runtime.h>
#include <cstdint>

// NodeDropout: out[e] = values[e] if neither endpoint is dropped, else 0.
// edge_index: int32 [2, E], values: f32 [E], nodes_flag: int32 [N]. Output: f32 [E].
//
// R7: 3-stage bulk pipeline for src/dst only (values read via direct coalesced
// LDG issued before the stage wait — its wavefront load is small enough to not
// re-create the R5 L1tex queue overflow). Bitmask (125 KB) smem-resident.
// Pack kernel parallelized to one word per warp (was latency-serialized).

static constexpr int MAX_WORDS = 32768;
__device__ unsigned int g_bits[MAX_WORDS];

static constexpr int THREADS      = 1024;
static constexpr int NCONS        = 31;            // consumer warps 0..30
static constexpr int GPT          = NCONS * 32;    // 992 float4-groups per tile
static constexpr int BUF_BYTES    = GPT * 16;      // 15872 B per index array per stage
static constexpr int STAGE_BYTES  = 2 * BUF_BYTES; // 31744 (src + dst only)
static constexpr int NSTAGES      = 3;
static constexpr int MBAR_OFF     = 0;             // full[s] at 16*s, empty[s] at 16*s+8
static constexpr int BUF_OFF      = 64;
static constexpr int BITS_OFF     = BUF_OFF + NSTAGES * STAGE_BYTES; // 95296

// ---- PTX helpers ----
__device__ __forceinline__ uint32_t smem_u32(const void* p) {
    return (uint32_t)__cvta_generic_to_shared(p);
}
__device__ __forceinline__ void mbar_init(uint32_t a, uint32_t cnt) {
    asm volatile("mbarrier.init.shared.b64 [%0], %1;" :: "r"(a), "r"(cnt) : "memory");
}
__device__ __forceinline__ void mbar_expect_tx(uint32_t a, uint32_t bytes) {
    asm volatile("mbarrier.arrive.expect_tx.shared.b64 _, [%0], %1;" :: "r"(a), "r"(bytes) : "memory");
}
__device__ __forceinline__ void mbar_arrive(uint32_t a) {
    asm volatile("mbarrier.arrive.shared.b64 _, [%0];" :: "r"(a) : "memory");
}
__device__ __forceinline__ void mbar_wait(uint32_t a, uint32_t parity) {
    uint32_t done = 0;
    while (!done) {
        asm volatile(
            "{\n\t.reg .pred p;\n\t"
            "mbarrier.try_wait.parity.shared.b64 p, [%1], %2;\n\t"
            "selp.b32 %0, 1, 0, p;\n\t}"
            : "=r"(done) : "r"(a), "r"(parity) : "memory");
    }
}
__device__ __forceinline__ void bulk_g2s(uint32_t dst, const void* src,
                                         uint32_t bytes, uint32_t mbar) {
    asm volatile(
        "cp.async.bulk.shared::cluster.global.mbarrier::complete_tx::bytes "
        "[%0], [%1], %2, [%3];"
        :: "r"(dst), "l"(src), "r"(bytes), "r"(mbar) : "memory");
}

// ---- Kernel 1: pack int32 flags -> bitmask, ONE word per warp ----
__global__ __launch_bounds__(1024)
void pack_flags_kernel(const int* __restrict__ flag, int nflags, int nwords) {
    int warp = (blockIdx.x * blockDim.x + threadIdx.x) >> 5;
    int lane = threadIdx.x & 31;
    if (warp >= nwords) return;
    int idx = (warp << 5) + lane;
    int f = (idx < nflags) ? flag[idx] : 0;
    unsigned int bits = __ballot_sync(0xFFFFFFFFu, f != 0);
    if (lane == 0) g_bits[warp] = bits;
}

// ---- Kernel 2: persistent pipelined main kernel ----
__global__ __launch_bounds__(THREADS, 1)
void node_dropout_kernel(const int4* __restrict__ src4,
                         const int4* __restrict__ dst4,
                         const float4* __restrict__ vals,
                         float4* __restrict__ out,
                         int n4, int ntiles, int nwords) {
    extern __shared__ __align__(16) unsigned char smem_raw[];
    unsigned int* s_bits = (unsigned int*)(smem_raw + BITS_OFF);
    uint32_t mbar_base = smem_u32(smem_raw + MBAR_OFF);
    int tid  = threadIdx.x;
    int warp = tid >> 5;
    int lane = tid & 31;

    // Stage bitmask into smem (coalesced; L2 hits after first CTA).
    for (int w = tid; w < nwords; w += THREADS)
        s_bits[w] = g_bits[w];

    if (tid == 0) {
        for (int s = 0; s < NSTAGES; s++) {
            mbar_init(mbar_base + 16 * s, 1);         // full
            mbar_init(mbar_base + 16 * s + 8, NCONS); // empty
        }
    }
    __syncthreads();

    if (warp == NCONS) {
        // ---- Producer warp: keep NSTAGES bulk transfers in flight ----
        int stage = 0, phase = 1;   // fresh barriers pass the first parity-1 waits
        for (int t = blockIdx.x; t < ntiles; t += gridDim.x) {
            int g0 = t * GPT;
            int cnt = min(GPT, n4 - g0);
            uint32_t bytes = (uint32_t)cnt * 16u;
            if (lane == 0) {
                uint32_t full  = mbar_base + 16 * stage;
                uint32_t empty = full + 8;
                mbar_wait(empty, phase);
                mbar_expect_tx(full, bytes * 2u);
                uint32_t base = smem_u32(smem_raw + BUF_OFF + stage * STAGE_BYTES);
                bulk_g2s(base,             src4 + g0, bytes, full);
                bulk_g2s(base + BUF_BYTES, dst4 + g0, bytes, full);
            }
            if (++stage == NSTAGES) { stage = 0; phase ^= 1; }
        }
    } else {
        // ---- Consumer warps 0..30 ----
        int stage = 0, phase = 0;
        int g = warp * 32 + lane;   // 0..991 within tile
        for (int t = blockIdx.x; t < ntiles; t += gridDim.x) {
            int g0 = t * GPT;
            int cnt = min(GPT, n4 - g0);
            bool act = (g < cnt);

            // Issue values LDG before the stage wait: overlaps DRAM latency.
            float4 v = make_float4(0.f, 0.f, 0.f, 0.f);
            if (act) v = __ldg(&vals[g0 + g]);

            uint32_t full = mbar_base + 16 * stage;
            mbar_wait(full, phase);   // acquire: orders bulk data before LDS

            if (act) {
                const unsigned char* sb = smem_raw + BUF_OFF + stage * STAGE_BYTES;
                int4 s = ((const int4*)(sb))[g];
                int4 d = ((const int4*)(sb + BUF_BYTES))[g];

                unsigned int b0 = (s_bits[((unsigned)s.x) >> 5] >> (s.x & 31)) |
                                  (s_bits[((unsigned)d.x) >> 5] >> (d.x & 31));
                unsigned int b1 = (s_bits[((unsigned)s.y) >> 5] >> (s.y & 31)) |
                                  (s_bits[((unsigned)d.y) >> 5] >> (d.y & 31));
                unsigned int b2 = (s_bits[((unsigned)s.z) >> 5] >> (s.z & 31)) |
                                  (s_bits[((unsigned)d.z) >> 5] >> (d.z & 31));
                unsigned int b3 = (s_bits[((unsigned)s.w) >> 5] >> (s.w & 31)) |
                                  (s_bits[((unsigned)d.w) >> 5] >> (d.w & 31));

                float4 o;
                o.x = (b0 & 1u) ? 0.0f : v.x;
                o.y = (b1 & 1u) ? 0.0f : v.y;
                o.z = (b2 & 1u) ? 0.0f : v.z;
                o.w = (b3 & 1u) ? 0.0f : v.w;
                out[g0 + g] = o;
            }
            __syncwarp();
            if (lane == 0) mbar_arrive(mbar_base + 16 * stage + 8);  // empty
            if (++stage == NSTAGES) { stage = 0; phase ^= 1; }
        }
    }
}

extern "C" void kernel_launch(void* const* d_in, const int* in_sizes, int n_in,
                              void* d_out, int out_size) {
    // metadata order: edge_index [2, E] int32, values [E] f32, nodes_flag [N] int32
    const int* edge_index = (const int*)d_in[0];
    const float* values = (const float*)d_in[1];
    const int* nodes_flag = (const int*)d_in[2];
    float* out = (float*)d_out;

    int e = in_sizes[1];
    int nflags = in_sizes[2];
    int n4 = e / 4;
    int nwords = (nflags + 31) / 32;
    int ntiles = (n4 + GPT - 1) / GPT;
    size_t smem_bytes = (size_t)BITS_OFF + (size_t)nwords * 4;

    const int* src = edge_index;
    const int* dst = edge_index + e;

    // Pack: one bitmask word per warp -> single LDG + ballot, no serialization.
    int pack_blocks = (nwords * 32 + 1023) / 1024;
    pack_flags_kernel<<<pack_blocks, 1024>>>(nodes_flag, nflags, nwords);

    int num_sms = 148;
    cudaDeviceGetAttribute(&num_sms, cudaDevAttrMultiProcessorCount, 0);
    cudaFuncSetAttribute(node_dropout_kernel,
                         cudaFuncAttributeMaxDynamicSharedMemorySize,
                         (int)smem_bytes);

    node_dropout_kernel<<<num_sms, THREADS, smem_bytes>>>(
        (const int4*)src, (const int4*)dst, (const float4*)values,
        (float4*)out, n4, ntiles, nwords);
}